// round 7
// baseline (speedup 1.0000x reference)
#include <cuda_runtime.h>
#include <cuda_bf16.h>
#include <cstddef>

#define N_NODES   32768
#define L_IN      3000
#define PER_GRAPH 64
#define NUM_GRAPHS 512
#define N_EDGES   524288
#define EPG       1024          // edges per graph
#define HID       128
#define OUT3      64
#define RED       146
#define F_IN      4672
#define KDIM      4672
#define EPSV      1e-5f

__device__ float g_h0[(size_t)N_NODES * F_IN];
__device__ float g_hlin1[(size_t)N_NODES * HID];
__device__ float g_dinv[N_NODES];

__device__ __forceinline__ unsigned long long ffma2(unsigned long long a,
                                                    unsigned long long b,
                                                    unsigned long long c) {
    unsigned long long d;
    asm("fma.rn.f32x2 %0, %1, %2, %3;" : "=l"(d) : "l"(a), "l"(b), "l"(c));
    return d;
}
__device__ __forceinline__ unsigned long long pack2(float lo, float hi) {
    unsigned long long d;
    asm("mov.b64 %0, {%1, %2};" : "=l"(d) : "f"(lo), "f"(hi));
    return d;
}
__device__ __forceinline__ float2 unpack2(unsigned long long v) {
    float2 r;
    asm("mov.b64 {%0, %1}, %2;" : "=f"(r.x), "=f"(r.y) : "l"(v));
    return r;
}

// ---------------- degree -> dinv ----------------
__global__ __launch_bounds__(256) void deg_kernel(const int* __restrict__ ei,
                                                  const float* __restrict__ ea) {
    __shared__ float degs[PER_GRAPH];
    const int g = blockIdx.x, tid = threadIdx.x;
    if (tid < PER_GRAPH) degs[tid] = 1.0f;           // self loop
    __syncthreads();
    const int* dstA = ei + N_EDGES;
    const int e0 = g * EPG, base = g * PER_GRAPH;
    for (int e = tid; e < EPG; e += 256)
        atomicAdd(&degs[dstA[e0 + e] - base], ea[e0 + e]);
    __syncthreads();
    if (tid < PER_GRAPH) g_dinv[base + tid] = rsqrtf(degs[tid]);
}

// ---------------- Conv1d(1->32,k=100,s=20)+bias+ReLU, 1 block/node ----------
__global__ __launch_bounds__(256) void conv_kernel(const float* __restrict__ x,
                                                   const float* __restrict__ cw,
                                                   const float* __restrict__ cb) {
    __shared__ __align__(16) float smem[7168];  // [0,3968) x padded; [3968,7168) w^T
    float* xs = smem;
    float* ws = smem + 3968;
    const int n = blockIdx.x, tid = threadIdx.x;

    const float* xr = x + (size_t)n * L_IN;
    for (int i = tid; i < 3968; i += 256) xs[i] = (i < L_IN) ? xr[i] : 0.0f;
    for (int i = tid; i < 3200; i += 256) {
        int f = i / 100, t = i - f * 100;
        ws[t * 32 + f] = cw[i];
    }
    __syncthreads();

    const int fg = tid & 3;       // 4 groups of 8 filters
    const int rg = tid >> 2;      // 64 groups of 3 positions
    const int rbase = rg * 3;

    unsigned long long acc[3][4];
#pragma unroll
    for (int j = 0; j < 3; ++j)
#pragma unroll
        for (int p = 0; p < 4; ++p) acc[j][p] = 0ull;

    const float* xb = xs + rg * 60;
    const float* wb = ws + fg * 8;
#pragma unroll 5
    for (int t = 0; t < 100; ++t) {
        float x0 = xb[t], x1 = xb[20 + t], x2 = xb[40 + t];
        unsigned long long xd0 = pack2(x0, x0), xd1 = pack2(x1, x1), xd2 = pack2(x2, x2);
        const float* wt = wb + t * 32;
        ulonglong2 wA = *(const ulonglong2*)(wt);
        ulonglong2 wB = *(const ulonglong2*)(wt + 4);
        acc[0][0] = ffma2(xd0, wA.x, acc[0][0]);
        acc[0][1] = ffma2(xd0, wA.y, acc[0][1]);
        acc[0][2] = ffma2(xd0, wB.x, acc[0][2]);
        acc[0][3] = ffma2(xd0, wB.y, acc[0][3]);
        acc[1][0] = ffma2(xd1, wA.x, acc[1][0]);
        acc[1][1] = ffma2(xd1, wA.y, acc[1][1]);
        acc[1][2] = ffma2(xd1, wB.x, acc[1][2]);
        acc[1][3] = ffma2(xd1, wB.y, acc[1][3]);
        acc[2][0] = ffma2(xd2, wA.x, acc[2][0]);
        acc[2][1] = ffma2(xd2, wA.y, acc[2][1]);
        acc[2][2] = ffma2(xd2, wB.x, acc[2][2]);
        acc[2][3] = ffma2(xd2, wB.y, acc[2][3]);
    }
    __syncthreads();                    // reuse smem as output staging
    float* os = smem;                   // 4672 floats: layout f*146+r
#pragma unroll
    for (int j = 0; j < 3; ++j) {
        int r = rbase + j;
        if (r < RED) {
#pragma unroll
            for (int p = 0; p < 4; ++p) {
                float2 v = unpack2(acc[j][p]);
                int f = fg * 8 + p * 2;
                float lo = v.x + cb[f], hi = v.y + cb[f + 1];
                os[f * RED + r]       = lo > 0.f ? lo : 0.f;
                os[(f + 1) * RED + r] = hi > 0.f ? hi : 0.f;
            }
        }
    }
    __syncthreads();
    float4* d4 = (float4*)(g_h0 + (size_t)n * F_IN);
    const float4* s4 = (const float4*)os;
    for (int i = tid; i < F_IN / 4; i += 256) d4[i] = s4[i];
}

// ---------------- GEMM1: hlin1[32768,128] = h0 @ W1 -------------------------
__global__ __launch_bounds__(256) void gemm1_kernel(const float* __restrict__ B) {
    __shared__ __align__(16) float As[2][16 * 128];  // [k][m]
    __shared__ __align__(16) float Bs[2][16 * 128];  // [k][n]
    const int tid = threadIdx.x;
    const int m0 = blockIdx.x * 128;
    const int tx = tid & 15, ty = tid >> 4;
    const int arow = tid >> 1, aseg = tid & 1;
    const int brow = tid >> 4, bcol = (tid & 15) * 8;

    const float* aptr = g_h0 + (size_t)(m0 + arow) * KDIM + aseg * 8;
    const float* bptr = B + brow * 128 + bcol;

    unsigned long long acc[8][4];
#pragma unroll
    for (int i = 0; i < 8; ++i)
#pragma unroll
        for (int p = 0; p < 4; ++p) acc[i][p] = 0ull;

    float4 ar0 = *(const float4*)(aptr);
    float4 ar1 = *(const float4*)(aptr + 4);
    float4 br0 = *(const float4*)(bptr);
    float4 br1 = *(const float4*)(bptr + 4);
    {
        float av[8] = {ar0.x, ar0.y, ar0.z, ar0.w, ar1.x, ar1.y, ar1.z, ar1.w};
#pragma unroll
        for (int j = 0; j < 8; ++j) As[0][(aseg * 8 + j) * 128 + arow] = av[j];
        *(float4*)&Bs[0][brow * 128 + bcol] = br0;
        *(float4*)&Bs[0][brow * 128 + bcol + 4] = br1;
    }
    __syncthreads();

    int buf = 0;
    const int NT = KDIM / 16;  // 292
    for (int kt = 0; kt < NT; ++kt) {
        if (kt < NT - 1) {
            const float* ap = aptr + (kt + 1) * 16;
            ar0 = *(const float4*)(ap);
            ar1 = *(const float4*)(ap + 4);
            const float* bp = bptr + (size_t)(kt + 1) * 16 * 128;
            br0 = *(const float4*)(bp);
            br1 = *(const float4*)(bp + 4);
        }
#pragma unroll
        for (int kk = 0; kk < 16; ++kk) {
            const float* asp = &As[buf][kk * 128];
            const float* bsp = &Bs[buf][kk * 128];
            float4 a0 = *(const float4*)(asp + ty * 4);
            float4 a1 = *(const float4*)(asp + 64 + ty * 4);
            ulonglong2 b0 = *(const ulonglong2*)(bsp + tx * 4);
            ulonglong2 b1 = *(const ulonglong2*)(bsp + 64 + tx * 4);
            unsigned long long ad[8] = {
                pack2(a0.x, a0.x), pack2(a0.y, a0.y), pack2(a0.z, a0.z), pack2(a0.w, a0.w),
                pack2(a1.x, a1.x), pack2(a1.y, a1.y), pack2(a1.z, a1.z), pack2(a1.w, a1.w)};
            unsigned long long bd[4] = {b0.x, b0.y, b1.x, b1.y};
#pragma unroll
            for (int i = 0; i < 8; ++i)
#pragma unroll
                for (int p = 0; p < 4; ++p)
                    acc[i][p] = ffma2(ad[i], bd[p], acc[i][p]);
        }
        if (kt < NT - 1) {
            float av[8] = {ar0.x, ar0.y, ar0.z, ar0.w, ar1.x, ar1.y, ar1.z, ar1.w};
            int nb = buf ^ 1;
#pragma unroll
            for (int j = 0; j < 8; ++j) As[nb][(aseg * 8 + j) * 128 + arow] = av[j];
            *(float4*)&Bs[nb][brow * 128 + bcol] = br0;
            *(float4*)&Bs[nb][brow * 128 + bcol + 4] = br1;
            __syncthreads();
            buf = nb;
        }
    }
#pragma unroll
    for (int i = 0; i < 8; ++i) {
        int m = m0 + ((i < 4) ? (ty * 4 + i) : (64 + ty * 4 + i - 4));
        float* crow = g_hlin1 + (size_t)m * 128;
#pragma unroll
        for (int p = 0; p < 4; ++p) {
            int nb2 = (p < 2) ? (tx * 4 + 2 * p) : (64 + tx * 4 + 2 * (p - 2));
            *(float2*)&crow[nb2] = unpack2(acc[i][p]);
        }
    }
}

// ---------------- per-graph tail helpers ------------------------------------
template <int C>
__device__ __forceinline__ void agg_layer(const float* __restrict__ hin,
                                          float* __restrict__ hout,
                                          const unsigned* __restrict__ eix,
                                          const float* __restrict__ enorm,
                                          const float* __restrict__ dv2,
                                          const float* __restrict__ bias,
                                          const float* __restrict__ gam,
                                          const float* __restrict__ bet,
                                          const float* __restrict__ mu,
                                          const float* __restrict__ var,
                                          int c) {
    float scale = gam[c] * rsqrtf(var[c] + EPSV);
    float shift = bet[c] - mu[c] * scale + bias[c] * scale;  // bias folded in
#pragma unroll 8
    for (int m = 0; m < PER_GRAPH; ++m)                      // self-loop term
        hout[m * C + c] = hin[m * C + c] * dv2[m];
#pragma unroll 4
    for (int e = 0; e < EPG; ++e) {
        unsigned p = eix[e];
        int s = p & 255, d = p >> 8;
        hout[d * C + c] += enorm[e] * hin[s * C + c];
    }
#pragma unroll 8
    for (int m = 0; m < PER_GRAPH; ++m) {
        float v = hout[m * C + c] * scale + shift;
        hout[m * C + c] = v > 0.f ? v : 0.f;
    }
}

// O[64,COUT] = A[64,128] @ W[128,COUT]; 256 threads
template <int COUT>
__device__ __forceinline__ void small_gemm128(const float* __restrict__ A,
                                              const float* __restrict__ W,
                                              float* __restrict__ O, int tid) {
    const int tx = tid & 15, ty = tid >> 4;
    constexpr int NP = (COUT == 128) ? 4 : 2;
    unsigned long long acc[4][NP];
#pragma unroll
    for (int i = 0; i < 4; ++i)
#pragma unroll
        for (int p = 0; p < NP; ++p) acc[i][p] = 0ull;
#pragma unroll 4
    for (int k = 0; k < 128; ++k) {
        const float* wr = W + k * COUT;
        unsigned long long bd[NP];
        ulonglong2 bq0 = *(const ulonglong2*)(wr + tx * 4);
        bd[0] = bq0.x; bd[1] = bq0.y;
        if constexpr (COUT == 128) {
            ulonglong2 bq1 = *(const ulonglong2*)(wr + 64 + tx * 4);
            bd[2] = bq1.x; bd[3] = bq1.y;
        }
#pragma unroll
        for (int i = 0; i < 4; ++i) {
            float a = A[(ty * 4 + i) * 128 + k];
            unsigned long long ad = pack2(a, a);
#pragma unroll
            for (int p = 0; p < NP; ++p) acc[i][p] = ffma2(ad, bd[p], acc[i][p]);
        }
    }
#pragma unroll
    for (int i = 0; i < 4; ++i) {
        float* orow = O + (ty * 4 + i) * COUT;
#pragma unroll
        for (int p = 0; p < NP; ++p) {
            int nb = (p < 2) ? (tx * 4 + 2 * p) : (64 + tx * 4 + 2 * (p - 2));
            *(float2*)&orow[nb] = unpack2(acc[i][p]);
        }
    }
}

// smem floats: hs 8192 | os 8192 | Wb 16384 | enorm 1024 | eix 1024 | dv 64 | dv2 64 | pooled 64
#define SM_FLOATS 35008
#define SM_BYTES  (SM_FLOATS * 4)

__global__ __launch_bounds__(256) void graph_kernel(
    const int* __restrict__ ei, const float* __restrict__ ea,
    const float* __restrict__ b1, const float* __restrict__ g1,
    const float* __restrict__ be1, const float* __restrict__ m1,
    const float* __restrict__ v1, const float* __restrict__ W2,
    const float* __restrict__ b2, const float* __restrict__ g2,
    const float* __restrict__ be2, const float* __restrict__ m2,
    const float* __restrict__ v2, const float* __restrict__ W3,
    const float* __restrict__ b3, const float* __restrict__ g3,
    const float* __restrict__ be3, const float* __restrict__ m3,
    const float* __restrict__ v3, const float* __restrict__ fcw,
    const float* __restrict__ fcb, float* __restrict__ out) {
    extern __shared__ float sm[];
    float* hs = sm;
    float* os = sm + 8192;
    float* Wb = sm + 16384;
    float* enorm = sm + 32768;
    unsigned* eix = (unsigned*)(sm + 33792);
    float* dv = sm + 34816;
    float* dv2 = sm + 34880;
    float* pooled = sm + 34944;

    const int g = blockIdx.x, tid = threadIdx.x;
    const int base = g << 6;

    if (tid < PER_GRAPH) {
        float d = g_dinv[base + tid];
        dv[tid] = d;
        dv2[tid] = d * d;
    }
    {
        const float4* s4 = (const float4*)(g_hlin1 + (size_t)base * HID);
        float4* d4 = (float4*)hs;
        for (int i = tid; i < 2048; i += 256) d4[i] = s4[i];
        const float4* w4 = (const float4*)W2;
        float4* wb4 = (float4*)Wb;
        for (int i = tid; i < 4096; i += 256) wb4[i] = w4[i];
    }
    __syncthreads();
    {
        const int* srcA = ei;
        const int* dstA = ei + N_EDGES;
        const int e0 = g << 10;
        for (int e = tid; e < EPG; e += 256) {
            int s = srcA[e0 + e] - base;
            int d = dstA[e0 + e] - base;
            eix[e] = (unsigned)s | ((unsigned)d << 8);
            enorm[e] = dv[s] * ea[e0 + e] * dv[d];
        }
    }
    __syncthreads();

    // layer 1: hs (hlin1) -> os (h1)
    if (tid < 128) agg_layer<128>(hs, os, eix, enorm, dv2, b1, g1, be1, m1, v1, tid);
    __syncthreads();
    // GEMM2: hs = h1 @ W2
    small_gemm128<128>(os, Wb, hs, tid);
    __syncthreads();
    // layer 2 (threads<128); threads>=128 prefetch W3 into Wb
    if (tid < 128) {
        agg_layer<128>(hs, os, eix, enorm, dv2, b2, g2, be2, m2, v2, tid);
    } else {
        const float4* w4 = (const float4*)W3;
        float4* wb4 = (float4*)Wb;
        for (int i = tid - 128; i < 2048; i += 128) wb4[i] = w4[i];
    }
    __syncthreads();
    // GEMM3: hs[64,64] = h2 @ W3
    small_gemm128<64>(os, Wb, hs, tid);
    __syncthreads();
    // layer 3: hs (hlin3) -> os (h3), stride 64
    if (tid < 64) agg_layer<64>(hs, os, eix, enorm, dv2, b3, g3, be3, m3, v3, tid);
    __syncthreads();
    // mean pool
    if (tid < 64) {
        float s = 0.f;
#pragma unroll 8
        for (int m = 0; m < PER_GRAPH; ++m) s += os[m * OUT3 + tid];
        pooled[tid] = s * (1.0f / 64.0f);
    }
    __syncthreads();
    // fc + log_softmax
    if (tid == 0) {
        float z0 = fcb[0], z1 = fcb[1];
#pragma unroll 8
        for (int c = 0; c < OUT3; ++c) {
            float p = pooled[c];
            z0 += p * fcw[2 * c];
            z1 += p * fcw[2 * c + 1];
        }
        float mx = fmaxf(z0, z1);
        float lse = mx + logf(expf(z0 - mx) + expf(z1 - mx));
        out[2 * g] = z0 - lse;
        out[2 * g + 1] = z1 - lse;
    }
}

extern "C" void kernel_launch(void* const* d_in, const int* in_sizes, int n_in,
                              void* d_out, int out_size) {
    const float* x   = (const float*)d_in[0];
    const int*   ei  = (const int*)d_in[1];
    const float* ea  = (const float*)d_in[2];
    const float* cw  = (const float*)d_in[4];
    const float* cb  = (const float*)d_in[5];
    const float* W1  = (const float*)d_in[6];
    const float* b1  = (const float*)d_in[7];
    const float* W2  = (const float*)d_in[8];
    const float* b2  = (const float*)d_in[9];
    const float* W3  = (const float*)d_in[10];
    const float* b3  = (const float*)d_in[11];
    const float* g1  = (const float*)d_in[12];
    const float* be1 = (const float*)d_in[13];
    const float* m1  = (const float*)d_in[14];
    const float* v1  = (const float*)d_in[15];
    const float* g2  = (const float*)d_in[16];
    const float* be2 = (const float*)d_in[17];
    const float* m2  = (const float*)d_in[18];
    const float* v2  = (const float*)d_in[19];
    const float* g3  = (const float*)d_in[20];
    const float* be3 = (const float*)d_in[21];
    const float* m3  = (const float*)d_in[22];
    const float* v3  = (const float*)d_in[23];
    const float* fcw = (const float*)d_in[24];
    const float* fcb = (const float*)d_in[25];
    float* out = (float*)d_out;

    cudaFuncSetAttribute(graph_kernel, cudaFuncAttributeMaxDynamicSharedMemorySize, SM_BYTES);

    deg_kernel<<<NUM_GRAPHS, 256>>>(ei, ea);
    conv_kernel<<<N_NODES, 256>>>(x, cw, cb);
    gemm1_kernel<<<N_NODES / 128, 256>>>(W1);
    graph_kernel<<<NUM_GRAPHS, 256, SM_BYTES>>>(
        ei, ea, b1, g1, be1, m1, v1, W2, b2, g2, be2, m2, v2,
        W3, b3, g3, be3, m3, v3, fcw, fcb, out);
}

// round 10
// speedup vs baseline: 1.0306x; 1.0306x over previous
#include <cuda_runtime.h>
#include <cuda_bf16.h>
#include <cstddef>

#define N_NODES    32768
#define L_IN       3000
#define PER_GRAPH  64
#define NUM_GRAPHS 512
#define N_EDGES    524288
#define EPG        1024
#define HID        128
#define OUT3       64
#define RED        146
#define F_IN       4672
#define KDIM       4672
#define EPSV       1e-5f

__device__ float g_h0[(size_t)N_NODES * F_IN];
__device__ float g_hlin1[(size_t)N_NODES * HID];

__device__ __forceinline__ unsigned long long ffma2(unsigned long long a,
                                                    unsigned long long b,
                                                    unsigned long long c) {
    unsigned long long d;
    asm("fma.rn.f32x2 %0, %1, %2, %3;" : "=l"(d) : "l"(a), "l"(b), "l"(c));
    return d;
}
__device__ __forceinline__ unsigned long long pack2(float lo, float hi) {
    unsigned long long d;
    asm("mov.b64 %0, {%1, %2};" : "=l"(d) : "f"(lo), "f"(hi));
    return d;
}
__device__ __forceinline__ float2 unpack2(unsigned long long v) {
    float2 r;
    asm("mov.b64 {%0, %1}, %2;" : "=f"(r.x), "=f"(r.y) : "l"(v));
    return r;
}

// ---------------------------------------------------------------------------
// Conv1d(1->32, k=100, s=20) + bias + ReLU. One block per node, 320 threads.
// 73 position-groups x 4 filter-groups = 292 active threads; 2 pos x 8 filt each.
// ---------------------------------------------------------------------------
__global__ __launch_bounds__(320) void conv_kernel(const float* __restrict__ x,
                                                   const float* __restrict__ cw,
                                                   const float* __restrict__ cb) {
    __shared__ __align__(16) float smem[6208];   // xs[3008] | ws[3200]
    float* xs = smem;
    float* ws = smem + 3008;
    const int n = blockIdx.x, tid = threadIdx.x;

    const float* xr = x + (size_t)n * L_IN;
    for (int i = tid; i < 3008; i += 320) xs[i] = (i < L_IN) ? xr[i] : 0.0f;
    for (int i = tid; i < 3200; i += 320) {
        int f = i / 100, t = i - f * 100;
        ws[t * 32 + f] = cw[i];                  // transpose: ws[t][f]
    }
    __syncthreads();

    const int rg = tid >> 2;                     // 0..79 (valid < 73)
    const int fg = tid & 3;
    const bool active = tid < 292;

    unsigned long long acc[2][4] = {};
    if (active) {
        const float* xb = xs + rg * 40;
        const float* wb = ws + fg * 8;
        for (int t = 0; t < 100; t += 4) {
            float4 xa = *(const float4*)(xb + t);
            float4 xc = *(const float4*)(xb + 20 + t);
            float xau[4] = {xa.x, xa.y, xa.z, xa.w};
            float xcu[4] = {xc.x, xc.y, xc.z, xc.w};
#pragma unroll
            for (int u = 0; u < 4; ++u) {
                unsigned long long xd0 = pack2(xau[u], xau[u]);
                unsigned long long xd1 = pack2(xcu[u], xcu[u]);
                const float* wt = wb + (t + u) * 32;
                ulonglong2 wA = *(const ulonglong2*)(wt);
                ulonglong2 wB = *(const ulonglong2*)(wt + 4);
                acc[0][0] = ffma2(xd0, wA.x, acc[0][0]);
                acc[0][1] = ffma2(xd0, wA.y, acc[0][1]);
                acc[0][2] = ffma2(xd0, wB.x, acc[0][2]);
                acc[0][3] = ffma2(xd0, wB.y, acc[0][3]);
                acc[1][0] = ffma2(xd1, wA.x, acc[1][0]);
                acc[1][1] = ffma2(xd1, wA.y, acc[1][1]);
                acc[1][2] = ffma2(xd1, wB.x, acc[1][2]);
                acc[1][3] = ffma2(xd1, wB.y, acc[1][3]);
            }
        }
    }
    __syncthreads();                             // xs/ws dead -> reuse as staging
    float* os = smem;                            // 4672 floats, layout f*146+r
    if (active) {
#pragma unroll
        for (int j = 0; j < 2; ++j) {
            int r = rg * 2 + j;
#pragma unroll
            for (int p = 0; p < 4; ++p) {
                float2 v = unpack2(acc[j][p]);
                int f = fg * 8 + 2 * p;
                float lo = v.x + cb[f], hi = v.y + cb[f + 1];
                os[f * RED + r]       = lo > 0.f ? lo : 0.f;
                os[(f + 1) * RED + r] = hi > 0.f ? hi : 0.f;
            }
        }
    }
    __syncthreads();
    float4* d4 = (float4*)(g_h0 + (size_t)n * F_IN);
    const float4* s4 = (const float4*)os;
    for (int i = tid; i < F_IN / 4; i += 320) d4[i] = s4[i];
}

// ---------------------------------------------------------------------------
// GEMM1: hlin1[32768,128] = h0 @ W1. 128x128x16 tiles, A pre-duplicated (a,a)
// pairs in smem so the inner loop is pure LDS.128 + FFMA2.
//   dyn smem: As 2*16*256 floats (32KB) | Bs 2*16*128 floats (16KB) = 48KB
// ---------------------------------------------------------------------------
__global__ __launch_bounds__(256) void gemm1_kernel(const float* __restrict__ B) {
    extern __shared__ float gsm[];
    float* As = gsm;             // buf*4096 + k*256 + 2*m  (dup pairs)
    float* Bs = gsm + 8192;      // buf*2048 + k*128 + n
    const int tid = threadIdx.x;
    const int m0 = blockIdx.x * 128;
    const int tx = tid & 15, ty = tid >> 4;
    const int arow = tid >> 1, aseg = tid & 1;
    const int brow = tid >> 4, bcol = (tid & 15) * 8;

    const float* aptr = g_h0 + (size_t)(m0 + arow) * KDIM + aseg * 8;
    const float* bptr = B + brow * 128 + bcol;

    unsigned long long acc[8][4] = {};

    float4 ar0 = *(const float4*)(aptr);
    float4 ar1 = *(const float4*)(aptr + 4);
    float4 br0 = *(const float4*)(bptr);
    float4 br1 = *(const float4*)(bptr + 4);
    {
        float av[8] = {ar0.x, ar0.y, ar0.z, ar0.w, ar1.x, ar1.y, ar1.z, ar1.w};
#pragma unroll
        for (int j = 0; j < 8; ++j)
            *(float2*)&As[(aseg * 8 + j) * 256 + 2 * arow] = make_float2(av[j], av[j]);
        *(float4*)&Bs[brow * 128 + bcol] = br0;
        *(float4*)&Bs[brow * 128 + bcol + 4] = br1;
    }
    __syncthreads();

    int buf = 0;
    const int NT = KDIM / 16;    // 292
    for (int kt = 0; kt < NT; ++kt) {
        if (kt < NT - 1) {
            const float* ap = aptr + (kt + 1) * 16;
            ar0 = *(const float4*)(ap);
            ar1 = *(const float4*)(ap + 4);
            const float* bp = bptr + (size_t)(kt + 1) * 16 * 128;
            br0 = *(const float4*)(bp);
            br1 = *(const float4*)(bp + 4);
        }
#pragma unroll
        for (int kk = 0; kk < 16; ++kk) {
            const float* asp = As + buf * 4096 + kk * 256;
            const float* bsp = Bs + buf * 2048 + kk * 128;
            ulonglong2 a01 = *(const ulonglong2*)(asp + 8 * ty);
            ulonglong2 a23 = *(const ulonglong2*)(asp + 8 * ty + 4);
            ulonglong2 a45 = *(const ulonglong2*)(asp + 128 + 8 * ty);
            ulonglong2 a67 = *(const ulonglong2*)(asp + 128 + 8 * ty + 4);
            ulonglong2 b0 = *(const ulonglong2*)(bsp + tx * 4);
            ulonglong2 b1 = *(const ulonglong2*)(bsp + 64 + tx * 4);
            unsigned long long ad[8] = {a01.x, a01.y, a23.x, a23.y,
                                        a45.x, a45.y, a67.x, a67.y};
            unsigned long long bd[4] = {b0.x, b0.y, b1.x, b1.y};
#pragma unroll
            for (int i = 0; i < 8; ++i)
#pragma unroll
                for (int p = 0; p < 4; ++p)
                    acc[i][p] = ffma2(ad[i], bd[p], acc[i][p]);
        }
        if (kt < NT - 1) {
            float av[8] = {ar0.x, ar0.y, ar0.z, ar0.w, ar1.x, ar1.y, ar1.z, ar1.w};
            int nb = buf ^ 1;
#pragma unroll
            for (int j = 0; j < 8; ++j)
                *(float2*)&As[nb * 4096 + (aseg * 8 + j) * 256 + 2 * arow] =
                    make_float2(av[j], av[j]);
            *(float4*)&Bs[nb * 2048 + brow * 128 + bcol] = br0;
            *(float4*)&Bs[nb * 2048 + brow * 128 + bcol + 4] = br1;
            __syncthreads();
            buf = nb;
        }
    }
#pragma unroll
    for (int i = 0; i < 8; ++i) {
        int m = m0 + ((i < 4) ? (ty * 4 + i) : (64 + ty * 4 + i - 4));
        float* crow = g_hlin1 + (size_t)m * 128;
#pragma unroll
        for (int p = 0; p < 4; ++p) {
            int nb2 = (p < 2) ? (tx * 4 + 2 * p) : (64 + tx * 4 + 2 * (p - 2));
            *(float2*)&crow[nb2] = unpack2(acc[i][p]);
        }
    }
}

// ---------------------------------------------------------------------------
// Per-graph tail: O[64,C] = A[64,K] @ W[K,C], optional BN+ReLU epilogue.
// 256 threads: 4 rows x (C/16) cols each.
// ---------------------------------------------------------------------------
template <int K, int C, int SA, bool BN>
__device__ __forceinline__ void tgemm(const float* __restrict__ A,
                                      const float* __restrict__ W,
                                      float* __restrict__ O,
                                      const float* __restrict__ scl,
                                      const float* __restrict__ shf, int tid) {
    const int tx = tid & 15, ty = tid >> 4;
    constexpr int NP = (C == 128) ? 4 : 2;
    unsigned long long acc[4][NP] = {};
#pragma unroll 2
    for (int k = 0; k < K; ++k) {
        const float* wr = W + k * C;
        unsigned long long bd[NP];
        ulonglong2 q0 = *(const ulonglong2*)(wr + tx * 4);
        bd[0] = q0.x; bd[1] = q0.y;
        if constexpr (C == 128) {
            ulonglong2 q1 = *(const ulonglong2*)(wr + 64 + tx * 4);
            bd[2] = q1.x; bd[3] = q1.y;
        }
#pragma unroll
        for (int i = 0; i < 4; ++i) {
            float a = A[(ty * 4 + i) * SA + k];
            unsigned long long ad = pack2(a, a);
#pragma unroll
            for (int p = 0; p < NP; ++p) acc[i][p] = ffma2(ad, bd[p], acc[i][p]);
        }
    }
#pragma unroll
    for (int i = 0; i < 4; ++i) {
        float* orow = O + (ty * 4 + i) * C;
#pragma unroll
        for (int p = 0; p < NP; ++p) {
            int nb = (p < 2) ? (tx * 4 + 2 * p) : (64 + tx * 4 + 2 * (p - 2));
            float2 v = unpack2(acc[i][p]);
            if (BN) {
                v.x = fmaxf(v.x * scl[nb] + shf[nb], 0.f);
                v.y = fmaxf(v.y * scl[nb + 1] + shf[nb + 1], 0.f);
            }
            *(float2*)&orow[nb] = v;
        }
    }
}

// smem floats: hs 8192 | os 8192 | Wb 16384 | M 4160 (64x65) | degs 64 |
//              dv 64 | scl 128 | shf 128 | pooled 64   = 37376
#define GK_FLOATS 37376
#define GK_BYTES  (GK_FLOATS * 4)

__global__ __launch_bounds__(256) void graph_kernel(
    const int* __restrict__ ei, const float* __restrict__ ea,
    const float* __restrict__ b1, const float* __restrict__ g1,
    const float* __restrict__ be1, const float* __restrict__ m1,
    const float* __restrict__ v1, const float* __restrict__ W2,
    const float* __restrict__ b2, const float* __restrict__ g2,
    const float* __restrict__ be2, const float* __restrict__ m2,
    const float* __restrict__ v2, const float* __restrict__ W3,
    const float* __restrict__ b3, const float* __restrict__ g3,
    const float* __restrict__ be3, const float* __restrict__ m3,
    const float* __restrict__ v3, const float* __restrict__ fcw,
    const float* __restrict__ fcb, float* __restrict__ out) {
    extern __shared__ float sm[];
    float* hs = sm;
    float* os = sm + 8192;
    float* Wb = sm + 16384;
    float* M  = sm + 32768;       // 64x65 padded
    float* degs = sm + 36928;
    float* dv = sm + 36992;
    float* scl = sm + 37056;
    float* shf = sm + 37184;
    float* pooled = sm + 37312;

    const int g = blockIdx.x, tid = threadIdx.x;
    const int base = g << 6, e0 = g << 10;
    const int* srcA = ei;
    const int* dstA = ei + N_EDGES;

    // degrees + zero M
    if (tid < 64) degs[tid] = 1.0f;              // self loop
    for (int i = tid; i < 64 * 65; i += 256) M[i] = 0.0f;
    __syncthreads();
    for (int e = tid; e < EPG; e += 256)
        atomicAdd(&degs[dstA[e0 + e] - base], ea[e0 + e]);
    __syncthreads();
    if (tid < 64) dv[tid] = rsqrtf(degs[tid]);
    __syncthreads();

    // build aggregation matrix; load hlin1 tile + W2; BN1 coefs
    if (tid < 64) M[tid * 65 + tid] = dv[tid] * dv[tid];
    for (int e = tid; e < EPG; e += 256) {
        int s = srcA[e0 + e] - base;
        int d = dstA[e0 + e] - base;
        atomicAdd(&M[d * 65 + s], dv[s] * ea[e0 + e] * dv[d]);
    }
    {
        const float4* s4 = (const float4*)(g_hlin1 + (size_t)base * HID);
        float4* d4 = (float4*)hs;
        for (int i = tid; i < 2048; i += 256) d4[i] = s4[i];
        const float4* w4 = (const float4*)W2;
        float4* wb4 = (float4*)Wb;
        for (int i = tid; i < 4096; i += 256) wb4[i] = w4[i];
    }
    if (tid < 128) {
        float sc = g1[tid] * rsqrtf(v1[tid] + EPSV);
        scl[tid] = sc;
        shf[tid] = be1[tid] - m1[tid] * sc + b1[tid] * sc;
    }
    __syncthreads();

    // layer 1 aggregation + BN + ReLU: os = M @ hs
    tgemm<64, 128, 65, true>(M, hs, os, scl, shf, tid);
    __syncthreads();
    // GEMM2: hs = h1 @ W2
    tgemm<128, 128, 128, false>(os, Wb, hs, nullptr, nullptr, tid);
    __syncthreads();
    // BN2 coefs + load W3
    if (tid < 128) {
        float sc = g2[tid] * rsqrtf(v2[tid] + EPSV);
        scl[tid] = sc;
        shf[tid] = be2[tid] - m2[tid] * sc + b2[tid] * sc;
    } else {
        const float4* w4 = (const float4*)W3;
        float4* wb4 = (float4*)Wb;
        for (int i = tid - 128; i < 2048; i += 128) wb4[i] = w4[i];
    }
    __syncthreads();
    // layer 2 aggregation: os = M @ hs
    tgemm<64, 128, 65, true>(M, hs, os, scl, shf, tid);
    __syncthreads();
    // GEMM3: hs[64,64] = h2 @ W3
    tgemm<128, 64, 128, false>(os, Wb, hs, nullptr, nullptr, tid);
    __syncthreads();
    if (tid < 64) {
        float sc = g3[tid] * rsqrtf(v3[tid] + EPSV);
        scl[tid] = sc;
        shf[tid] = be3[tid] - m3[tid] * sc + b3[tid] * sc;
    }
    __syncthreads();
    // layer 3 aggregation: os = M @ hs
    tgemm<64, 64, 65, true>(M, hs, os, scl, shf, tid);
    __syncthreads();

    // mean pool
    if (tid < 64) {
        float s = 0.f;
#pragma unroll 8
        for (int m = 0; m < PER_GRAPH; ++m) s += os[m * OUT3 + tid];
        pooled[tid] = s * (1.0f / 64.0f);
    }
    __syncthreads();
    // fc + log_softmax
    if (tid == 0) {
        float z0 = fcb[0], z1 = fcb[1];
#pragma unroll 8
        for (int c = 0; c < OUT3; ++c) {
            float p = pooled[c];
            z0 += p * fcw[2 * c];
            z1 += p * fcw[2 * c + 1];
        }
        float mx = fmaxf(z0, z1);
        float lse = mx + logf(expf(z0 - mx) + expf(z1 - mx));
        out[2 * g] = z0 - lse;
        out[2 * g + 1] = z1 - lse;
    }
}

extern "C" void kernel_launch(void* const* d_in, const int* in_sizes, int n_in,
                              void* d_out, int out_size) {
    const float* x   = (const float*)d_in[0];
    const int*   ei  = (const int*)d_in[1];
    const float* ea  = (const float*)d_in[2];
    const float* cw  = (const float*)d_in[4];
    const float* cb  = (const float*)d_in[5];
    const float* W1  = (const float*)d_in[6];
    const float* b1  = (const float*)d_in[7];
    const float* W2  = (const float*)d_in[8];
    const float* b2  = (const float*)d_in[9];
    const float* W3  = (const float*)d_in[10];
    const float* b3  = (const float*)d_in[11];
    const float* g1  = (const float*)d_in[12];
    const float* be1 = (const float*)d_in[13];
    const float* m1  = (const float*)d_in[14];
    const float* v1  = (const float*)d_in[15];
    const float* g2  = (const float*)d_in[16];
    const float* be2 = (const float*)d_in[17];
    const float* m2  = (const float*)d_in[18];
    const float* v2  = (const float*)d_in[19];
    const float* g3  = (const float*)d_in[20];
    const float* be3 = (const float*)d_in[21];
    const float* m3  = (const float*)d_in[22];
    const float* v3  = (const float*)d_in[23];
    const float* fcw = (const float*)d_in[24];
    const float* fcb = (const float*)d_in[25];
    float* out = (float*)d_out;

    cudaFuncSetAttribute(gemm1_kernel, cudaFuncAttributeMaxDynamicSharedMemorySize, 49152);
    cudaFuncSetAttribute(graph_kernel, cudaFuncAttributeMaxDynamicSharedMemorySize, GK_BYTES);

    conv_kernel<<<N_NODES, 320>>>(x, cw, cb);
    gemm1_kernel<<<N_NODES / 128, 256, 49152>>>(W1);
    graph_kernel<<<NUM_GRAPHS, 256, GK_BYTES>>>(
        ei, ea, b1, g1, be1, m1, v1, W2, b2, g2, be2, m2, v2,
        W3, b3, g3, be3, m3, v3, fcw, fcb, out);
}

// round 13
// speedup vs baseline: 1.3474x; 1.3075x over previous
#include <cuda_runtime.h>
#include <cuda_bf16.h>
#include <cstddef>
#include <cstdint>

#define N_NODES    32768
#define L_IN       3000
#define PER_GRAPH  64
#define NUM_GRAPHS 512
#define N_EDGES    524288
#define EPG        1024
#define HID        128
#define OUT3       64
#define RED        146
#define F_IN       4672
#define KDIM       4672
#define EPSV       1e-5f
#define ROWB       9344            // 4672 bf16 bytes per row

__device__ __nv_bfloat16 g_h0h[(size_t)N_NODES * F_IN];
__device__ __nv_bfloat16 g_h0l[(size_t)N_NODES * F_IN];
__device__ __nv_bfloat16 g_w1h[(size_t)HID * KDIM];
__device__ __nv_bfloat16 g_w1l[(size_t)HID * KDIM];
__device__ float g_hlin1[(size_t)N_NODES * HID];

__device__ __forceinline__ unsigned long long ffma2(unsigned long long a,
                                                    unsigned long long b,
                                                    unsigned long long c) {
    unsigned long long d;
    asm("fma.rn.f32x2 %0, %1, %2, %3;" : "=l"(d) : "l"(a), "l"(b), "l"(c));
    return d;
}
__device__ __forceinline__ unsigned long long pack2(float lo, float hi) {
    unsigned long long d;
    asm("mov.b64 %0, {%1, %2};" : "=l"(d) : "f"(lo), "f"(hi));
    return d;
}
__device__ __forceinline__ float2 unpack2(unsigned long long v) {
    float2 r;
    asm("mov.b64 {%0, %1}, %2;" : "=f"(r.x), "=f"(r.y) : "l"(v));
    return r;
}
__device__ __forceinline__ uint32_t s2u(const void* p) {
    uint32_t a;
    asm("{ .reg .u64 t; cvta.to.shared.u64 t, %1; cvt.u32.u64 %0, t; }"
        : "=r"(a) : "l"(p));
    return a;
}

// ---------------------------------------------------------------------------
// Conv1d(1->32, k=100, s=20) + bias + ReLU; emits bf16 hi/lo split of h0.
// ---------------------------------------------------------------------------
__global__ __launch_bounds__(320) void conv_kernel(const float* __restrict__ x,
                                                   const float* __restrict__ cw,
                                                   const float* __restrict__ cb) {
    __shared__ __align__(16) float smem[6208];   // xs[3008] | ws[3200]
    float* xs = smem;
    float* ws = smem + 3008;
    const int n = blockIdx.x, tid = threadIdx.x;

    const float* xr = x + (size_t)n * L_IN;
    for (int i = tid; i < 3008; i += 320) xs[i] = (i < L_IN) ? xr[i] : 0.0f;
    for (int i = tid; i < 3200; i += 320) {
        int f = i / 100, t = i - f * 100;
        ws[t * 32 + f] = cw[i];
    }
    __syncthreads();

    const int rg = tid >> 2;
    const int fg = tid & 3;
    const bool active = tid < 292;

    unsigned long long acc[2][4] = {};
    if (active) {
        const float* xb = xs + rg * 40;
        const float* wb = ws + fg * 8;
        for (int t = 0; t < 100; t += 4) {
            float4 xa = *(const float4*)(xb + t);
            float4 xc = *(const float4*)(xb + 20 + t);
            float xau[4] = {xa.x, xa.y, xa.z, xa.w};
            float xcu[4] = {xc.x, xc.y, xc.z, xc.w};
#pragma unroll
            for (int u = 0; u < 4; ++u) {
                unsigned long long xd0 = pack2(xau[u], xau[u]);
                unsigned long long xd1 = pack2(xcu[u], xcu[u]);
                const float* wt = wb + (t + u) * 32;
                ulonglong2 wA = *(const ulonglong2*)(wt);
                ulonglong2 wB = *(const ulonglong2*)(wt + 4);
                acc[0][0] = ffma2(xd0, wA.x, acc[0][0]);
                acc[0][1] = ffma2(xd0, wA.y, acc[0][1]);
                acc[0][2] = ffma2(xd0, wB.x, acc[0][2]);
                acc[0][3] = ffma2(xd0, wB.y, acc[0][3]);
                acc[1][0] = ffma2(xd1, wA.x, acc[1][0]);
                acc[1][1] = ffma2(xd1, wA.y, acc[1][1]);
                acc[1][2] = ffma2(xd1, wB.x, acc[1][2]);
                acc[1][3] = ffma2(xd1, wB.y, acc[1][3]);
            }
        }
    }
    __syncthreads();
    float* os = smem;                            // 4672 floats, layout f*146+r
    if (active) {
#pragma unroll
        for (int j = 0; j < 2; ++j) {
            int r = rg * 2 + j;
#pragma unroll
            for (int p = 0; p < 4; ++p) {
                float2 v = unpack2(acc[j][p]);
                int f = fg * 8 + 2 * p;
                float lo = v.x + cb[f], hi = v.y + cb[f + 1];
                os[f * RED + r]       = lo > 0.f ? lo : 0.f;
                os[(f + 1) * RED + r] = hi > 0.f ? hi : 0.f;
            }
        }
    }
    __syncthreads();
    __nv_bfloat16* hh = g_h0h + (size_t)n * F_IN;
    __nv_bfloat16* hl = g_h0l + (size_t)n * F_IN;
    for (int i = tid; i < F_IN / 8; i += 320) {
        float4 v0 = ((const float4*)os)[2 * i];
        float4 v1 = ((const float4*)os)[2 * i + 1];
        float vv[8] = {v0.x, v0.y, v0.z, v0.w, v1.x, v1.y, v1.z, v1.w};
        unsigned hw[4], lw[4];
#pragma unroll
        for (int j = 0; j < 4; ++j) {
            __nv_bfloat16 ha = __float2bfloat16(vv[2 * j]);
            __nv_bfloat16 hb = __float2bfloat16(vv[2 * j + 1]);
            __nv_bfloat16 la = __float2bfloat16(vv[2 * j] - __bfloat162float(ha));
            __nv_bfloat16 lb = __float2bfloat16(vv[2 * j + 1] - __bfloat162float(hb));
            hw[j] = (unsigned)__bfloat16_as_ushort(ha) |
                    ((unsigned)__bfloat16_as_ushort(hb) << 16);
            lw[j] = (unsigned)__bfloat16_as_ushort(la) |
                    ((unsigned)__bfloat16_as_ushort(lb) << 16);
        }
        ((uint4*)hh)[i] = make_uint4(hw[0], hw[1], hw[2], hw[3]);
        ((uint4*)hl)[i] = make_uint4(lw[0], lw[1], lw[2], lw[3]);
    }
}

// ---------------------------------------------------------------------------
// W1 prep: transpose [4672,128] f32 -> [128,4672] bf16 hi/lo (K-major rows)
// ---------------------------------------------------------------------------
__global__ __launch_bounds__(256) void w1prep_kernel(const float* __restrict__ W1) {
    int i = blockIdx.x * 256 + threadIdx.x;
    if (i >= KDIM * HID) return;
    int k = i >> 7, n = i & 127;
    float v = W1[i];
    __nv_bfloat16 h = __float2bfloat16(v);
    __nv_bfloat16 l = __float2bfloat16(v - __bfloat162float(h));
    g_w1h[(size_t)n * KDIM + k] = h;
    g_w1l[(size_t)n * KDIM + k] = l;
}

// ---------------------------------------------------------------------------
// GEMM1 via legacy tensor path (mma.sync bf16, baseline PTX -> HMMA):
// hlin1[32768,128] = h0 @ W1, 3-term bf16 split, fp32 accumulate.
// CTA 128x128, K-stage 32; 8 warps as 4(M) x 2(N), warp tile 32x64.
// smem: 2 stages x 4 arrays {Ah,Al,Bh,Bl} x 128 rows x 80B = 81920 B.
// ---------------------------------------------------------------------------
#define GS_ARR   10240           // 128 rows * 80 B
#define GS_STAGE 40960
#define GS_SMEM  81920

__device__ __forceinline__ void ldsm4(uint32_t& r0, uint32_t& r1, uint32_t& r2,
                                      uint32_t& r3, uint32_t a) {
    asm volatile("ldmatrix.sync.aligned.m8n8.x4.shared.b16 {%0,%1,%2,%3}, [%4];"
                 : "=r"(r0), "=r"(r1), "=r"(r2), "=r"(r3) : "r"(a));
}
__device__ __forceinline__ void mma16816(float* c, const uint32_t* a,
                                         const uint32_t* b) {
    asm volatile(
        "mma.sync.aligned.m16n8k16.row.col.f32.bf16.bf16.f32 "
        "{%0,%1,%2,%3}, {%4,%5,%6,%7}, {%8,%9}, {%0,%1,%2,%3};"
        : "+f"(c[0]), "+f"(c[1]), "+f"(c[2]), "+f"(c[3])
        : "r"(a[0]), "r"(a[1]), "r"(a[2]), "r"(a[3]), "r"(b[0]), "r"(b[1]));
}

__global__ __launch_bounds__(256) void gemm1_hmma() {
    extern __shared__ char smc[];
    const int tid = threadIdx.x, wid = tid >> 5, lid = tid & 31;
    const int m0 = blockIdx.x * 128;
    const int wm = wid & 3, wn = wid >> 2;        // warp tile origin
    const uint32_t sb = s2u(smc);

    const char* arrp[4] = {
        (const char*)g_h0h + (size_t)m0 * ROWB,
        (const char*)g_h0l + (size_t)m0 * ROWB,
        (const char*)g_w1h,
        (const char*)g_w1l};

    // async stage loader: 4 arrays x 128 rows x 64B
    auto load_stage = [&](int kt, int st) {
#pragma unroll
        for (int i = 0; i < 8; ++i) {
            int c = tid + i * 256;                // 0..2047
            int seg = c & 3;
            int row = (c >> 2) & 127;
            int arr = c >> 9;
            const char* g = arrp[arr] + (size_t)row * ROWB + kt * 64 + seg * 16;
            uint32_t d = sb + st * GS_STAGE + arr * GS_ARR + row * 80 + seg * 16;
            asm volatile("cp.async.ca.shared.global [%0], [%1], 16;"
                         :: "r"(d), "l"(g) : "memory");
        }
        asm volatile("cp.async.commit_group;" ::: "memory");
    };

    float acc[2][8][4] = {};

    load_stage(0, 0);

    const int NSTAGE = KDIM / 32;                 // 146
    for (int kt = 0; kt < NSTAGE; ++kt) {
        int b = kt & 1;
        if (kt + 1 < NSTAGE) {
            load_stage(kt + 1, b ^ 1);
            asm volatile("cp.async.wait_group 1;" ::: "memory");
        } else {
            asm volatile("cp.async.wait_group 0;" ::: "memory");
        }
        __syncthreads();

        const uint32_t stb = sb + b * GS_STAGE;
        const int q = lid >> 3;
#pragma unroll
        for (int kk = 0; kk < 2; ++kk) {
            // ---- A fragments (2 m16 tiles per array) ----
            uint32_t Ah[2][4], Al[2][4];
            {
                uint32_t arow = (q & 1) * 8 + (lid & 7);
                uint32_t acol = kk * 32 + (q >> 1) * 16;
#pragma unroll
                for (int mt = 0; mt < 2; ++mt) {
                    uint32_t r = wm * 32 + mt * 16 + arow;
                    ldsm4(Ah[mt][0], Ah[mt][1], Ah[mt][2], Ah[mt][3],
                          stb + r * 80 + acol);
                    ldsm4(Al[mt][0], Al[mt][1], Al[mt][2], Al[mt][3],
                          stb + GS_ARR + r * 80 + acol);
                }
            }
            // ---- B fragments: 8 n8 tiles per array (4 x ldsm4, 2 tiles each) ----
            uint32_t Bh[8][2], Bl[8][2];
            {
                uint32_t brow = (q >> 1) * 8 + (lid & 7);
                uint32_t bcol = kk * 32 + (q & 1) * 16;
#pragma unroll
                for (int g2 = 0; g2 < 4; ++g2) {
                    uint32_t r = wn * 64 + g2 * 16 + brow;
                    ldsm4(Bh[2 * g2][0], Bh[2 * g2][1], Bh[2 * g2 + 1][0],
                          Bh[2 * g2 + 1][1], stb + 2 * GS_ARR + r * 80 + bcol);
                    ldsm4(Bl[2 * g2][0], Bl[2 * g2][1], Bl[2 * g2 + 1][0],
                          Bl[2 * g2 + 1][1], stb + 3 * GS_ARR + r * 80 + bcol);
                }
            }
            // ---- 3-term accumulate ----
#pragma unroll
            for (int mt = 0; mt < 2; ++mt)
#pragma unroll
                for (int nt = 0; nt < 8; ++nt) {
                    mma16816(acc[mt][nt], Ah[mt], Bh[nt]);
                    mma16816(acc[mt][nt], Ah[mt], Bl[nt]);
                    mma16816(acc[mt][nt], Al[mt], Bh[nt]);
                }
        }
        __syncthreads();
    }

    // epilogue: fp32 accumulators -> g_hlin1
    const int gr = lid >> 2, tc = lid & 3;
#pragma unroll
    for (int mt = 0; mt < 2; ++mt) {
        int row0 = m0 + wm * 32 + mt * 16 + gr;
#pragma unroll
        for (int nt = 0; nt < 8; ++nt) {
            int col = wn * 64 + nt * 8 + 2 * tc;
            *(float2*)&g_hlin1[(size_t)row0 * 128 + col] =
                make_float2(acc[mt][nt][0], acc[mt][nt][1]);
            *(float2*)&g_hlin1[(size_t)(row0 + 8) * 128 + col] =
                make_float2(acc[mt][nt][2], acc[mt][nt][3]);
        }
    }
}

// ---------------------------------------------------------------------------
// Per-graph tail: O[64,C] = A[64,K] @ W[K,C] (+BN+ReLU). 256 threads.
// ---------------------------------------------------------------------------
template <int K, int C, int SA, bool BN>
__device__ __forceinline__ void tgemm(const float* __restrict__ A,
                                      const float* __restrict__ W,
                                      float* __restrict__ O,
                                      const float* __restrict__ scl,
                                      const float* __restrict__ shf, int tid) {
    const int tx = tid & 15, ty = tid >> 4;
    constexpr int NP = (C == 128) ? 4 : 2;
    unsigned long long acc[4][NP] = {};
#pragma unroll 2
    for (int k = 0; k < K; ++k) {
        const float* wr = W + k * C;
        unsigned long long bd[NP];
        ulonglong2 q0 = *(const ulonglong2*)(wr + tx * 4);
        bd[0] = q0.x; bd[1] = q0.y;
        if constexpr (C == 128) {
            ulonglong2 q1 = *(const ulonglong2*)(wr + 64 + tx * 4);
            bd[2] = q1.x; bd[3] = q1.y;
        }
#pragma unroll
        for (int i = 0; i < 4; ++i) {
            float a = A[(ty * 4 + i) * SA + k];
            unsigned long long ad = pack2(a, a);
#pragma unroll
            for (int p = 0; p < NP; ++p) acc[i][p] = ffma2(ad, bd[p], acc[i][p]);
        }
    }
#pragma unroll
    for (int i = 0; i < 4; ++i) {
        float* orow = O + (ty * 4 + i) * C;
#pragma unroll
        for (int p = 0; p < NP; ++p) {
            int nb = (p < 2) ? (tx * 4 + 2 * p) : (64 + tx * 4 + 2 * (p - 2));
            float2 v = unpack2(acc[i][p]);
            if (BN) {
                v.x = fmaxf(v.x * scl[nb] + shf[nb], 0.f);
                v.y = fmaxf(v.y * scl[nb + 1] + shf[nb + 1], 0.f);
            }
            *(float2*)&orow[nb] = v;
        }
    }
}

#define GK_FLOATS 37376
#define GK_BYTES  (GK_FLOATS * 4)

__global__ __launch_bounds__(256) void graph_kernel(
    const int* __restrict__ ei, const float* __restrict__ ea,
    const float* __restrict__ b1, const float* __restrict__ g1,
    const float* __restrict__ be1, const float* __restrict__ m1,
    const float* __restrict__ v1, const float* __restrict__ W2,
    const float* __restrict__ b2, const float* __restrict__ g2,
    const float* __restrict__ be2, const float* __restrict__ m2,
    const float* __restrict__ v2, const float* __restrict__ W3,
    const float* __restrict__ b3, const float* __restrict__ g3,
    const float* __restrict__ be3, const float* __restrict__ m3,
    const float* __restrict__ v3, const float* __restrict__ fcw,
    const float* __restrict__ fcb, float* __restrict__ out) {
    extern __shared__ float sm[];
    float* hs = sm;
    float* os = sm + 8192;
    float* Wb = sm + 16384;
    float* M  = sm + 32768;       // 64x65 padded
    float* degs = sm + 36928;
    float* dv = sm + 36992;
    float* scl = sm + 37056;
    float* shf = sm + 37184;
    float* pooled = sm + 37312;

    const int g = blockIdx.x, tid = threadIdx.x;
    const int base = g << 6, e0 = g << 10;
    const int* srcA = ei;
    const int* dstA = ei + N_EDGES;

    if (tid < 64) degs[tid] = 1.0f;
    for (int i = tid; i < 64 * 65; i += 256) M[i] = 0.0f;
    __syncthreads();
    for (int e = tid; e < EPG; e += 256)
        atomicAdd(&degs[dstA[e0 + e] - base], ea[e0 + e]);
    __syncthreads();
    if (tid < 64) dv[tid] = rsqrtf(degs[tid]);
    __syncthreads();

    if (tid < 64) M[tid * 65 + tid] = dv[tid] * dv[tid];
    for (int e = tid; e < EPG; e += 256) {
        int s = srcA[e0 + e] - base;
        int d = dstA[e0 + e] - base;
        atomicAdd(&M[d * 65 + s], dv[s] * ea[e0 + e] * dv[d]);
    }
    {
        const float4* s4 = (const float4*)(g_hlin1 + (size_t)base * HID);
        float4* d4 = (float4*)hs;
        for (int i = tid; i < 2048; i += 256) d4[i] = s4[i];
        const float4* w4 = (const float4*)W2;
        float4* wb4 = (float4*)Wb;
        for (int i = tid; i < 4096; i += 256) wb4[i] = w4[i];
    }
    if (tid < 128) {
        float sc = g1[tid] * rsqrtf(v1[tid] + EPSV);
        scl[tid] = sc;
        shf[tid] = be1[tid] - m1[tid] * sc + b1[tid] * sc;
    }
    __syncthreads();

    tgemm<64, 128, 65, true>(M, hs, os, scl, shf, tid);
    __syncthreads();
    tgemm<128, 128, 128, false>(os, Wb, hs, nullptr, nullptr, tid);
    __syncthreads();
    if (tid < 128) {
        float sc = g2[tid] * rsqrtf(v2[tid] + EPSV);
        scl[tid] = sc;
        shf[tid] = be2[tid] - m2[tid] * sc + b2[tid] * sc;
    } else {
        const float4* w4 = (const float4*)W3;
        float4* wb4 = (float4*)Wb;
        for (int i = tid - 128; i < 2048; i += 128) wb4[i] = w4[i];
    }
    __syncthreads();
    tgemm<64, 128, 65, true>(M, hs, os, scl, shf, tid);
    __syncthreads();
    tgemm<128, 64, 128, false>(os, Wb, hs, nullptr, nullptr, tid);
    __syncthreads();
    if (tid < 64) {
        float sc = g3[tid] * rsqrtf(v3[tid] + EPSV);
        scl[tid] = sc;
        shf[tid] = be3[tid] - m3[tid] * sc + b3[tid] * sc;
    }
    __syncthreads();
    tgemm<64, 64, 65, true>(M, hs, os, scl, shf, tid);
    __syncthreads();

    if (tid < 64) {
        float s = 0.f;
#pragma unroll 8
        for (int m = 0; m < PER_GRAPH; ++m) s += os[m * OUT3 + tid];
        pooled[tid] = s * (1.0f / 64.0f);
    }
    __syncthreads();
    if (tid == 0) {
        float z0 = fcb[0], z1 = fcb[1];
#pragma unroll 8
        for (int c = 0; c < OUT3; ++c) {
            float p = pooled[c];
            z0 += p * fcw[2 * c];
            z1 += p * fcw[2 * c + 1];
        }
        float mx = fmaxf(z0, z1);
        float lse = mx + logf(expf(z0 - mx) + expf(z1 - mx));
        out[2 * g] = z0 - lse;
        out[2 * g + 1] = z1 - lse;
    }
}

extern "C" void kernel_launch(void* const* d_in, const int* in_sizes, int n_in,
                              void* d_out, int out_size) {
    const float* x   = (const float*)d_in[0];
    const int*   ei  = (const int*)d_in[1];
    const float* ea  = (const float*)d_in[2];
    const float* cw  = (const float*)d_in[4];
    const float* cb  = (const float*)d_in[5];
    const float* W1  = (const float*)d_in[6];
    const float* b1  = (const float*)d_in[7];
    const float* W2  = (const float*)d_in[8];
    const float* b2  = (const float*)d_in[9];
    const float* W3  = (const float*)d_in[10];
    const float* b3  = (const float*)d_in[11];
    const float* g1  = (const float*)d_in[12];
    const float* be1 = (const float*)d_in[13];
    const float* m1  = (const float*)d_in[14];
    const float* v1  = (const float*)d_in[15];
    const float* g2  = (const float*)d_in[16];
    const float* be2 = (const float*)d_in[17];
    const float* m2  = (const float*)d_in[18];
    const float* v2  = (const float*)d_in[19];
    const float* g3  = (const float*)d_in[20];
    const float* be3 = (const float*)d_in[21];
    const float* m3  = (const float*)d_in[22];
    const float* v3  = (const float*)d_in[23];
    const float* fcw = (const float*)d_in[24];
    const float* fcb = (const float*)d_in[25];
    float* out = (float*)d_out;

    cudaFuncSetAttribute(gemm1_hmma, cudaFuncAttributeMaxDynamicSharedMemorySize, GS_SMEM);
    cudaFuncSetAttribute(graph_kernel, cudaFuncAttributeMaxDynamicSharedMemorySize, GK_BYTES);

    conv_kernel<<<N_NODES, 320>>>(x, cw, cb);
    w1prep_kernel<<<(KDIM * HID + 255) / 256, 256>>>(W1);
    gemm1_hmma<<<N_NODES / 128, 256, GS_SMEM>>>();
    graph_kernel<<<NUM_GRAPHS, 256, GK_BYTES>>>(
        ei, ea, b1, g1, be1, m1, v1, W2, b2, g2, be2, m2, v2,
        W3, b3, g3, be3, m3, v3, fcw, fcb, out);
}